// round 15
// baseline (speedup 1.0000x reference)
#include <cuda_runtime.h>
#include <cuda_bf16.h>

// MoERouter — FINAL+ (R15 resubmit of R14: warp-local sync; prior round was
// an infra failure, not a kernel signal).
// Confirmed base: 80.29-80.89us over 5 runs, rel_err 6.4e-6.
//
// Design rationale (full measured sweep):
//  * Math: scores[b][e] = st(d+0.5)*st(0.5-d), d=x-e, SCALE=20. Only experts
//    {m-1, m, m+1} (m = nearest int) exceed ~2.3e-5 -> rest written as exact 0.
//    Closed form with u=|x-e|, z=20u, P=exp(-z), S=1+P, A=exp(-20):
//      score = P*(20S+zP)*(20S-z) / (400*(P+A)*S^2)
//    = 1 EX2 + 1 RCP per nonzero element. argmax = m analytically; exact tie
//    x=k+0.5 -> lower index (jnp.argmax first-max semantics).
//  * Stores: compulsory 553MB write stream binds at ~6.9TB/s (~86% of spec).
//    Sweep: .cs beats default & .wt (+8.4us); STG.128 beats STG.256 (+7.6us);
//    8KB contiguous warp runs beat 4KB-strided (+8.9us) and 16KB (+3.5us);
//    RPB 256 == 128, 512 regresses (+3.4us).
//  * R14/R15 delta: phase-1 producers and phase-2 consumers of each SMEM row
//    are the SAME warp (warp w covers rows [w*32,w*32+32) in both phases), so
//    __syncthreads -> __syncwarp: each warp starts streaming as soon as ITS
//    window math is done instead of waiting on the block's slowest warp.

#define RPB 256
#define NTHREADS 256

__global__ __launch_bounds__(NTHREADS)
void moe_router_kernel(const float* __restrict__ opcode,
                       float* __restrict__ scores_out,
                       float* __restrict__ idx_out)
{
    __shared__ float4 q[2][RPB];   // q[d][r]: float4 for chunk c0(r)+d
    __shared__ int    c0s[RPB];

    const int tid  = threadIdx.x;
    const int row0 = blockIdx.x * RPB;

    // ---------------- Phase 1: per-row window ----------------
    {
        const int b = row0 + tid;
        const float x = __ldg(opcode + b);

        float m = floorf(x + 0.5f);
        if (m - x == 0.5f) m -= 1.0f;      // exact tie -> lower index
        m = fminf(m, 63.0f);
        __stcs(idx_out + b, m);

        const float s  = fmaxf(m - 1.0f, 0.0f);
        const int   si = (int)s;
        const int   c0 = si >> 2;
        const int   off0 = si & 3;

        const float Aexp = 2.0611536e-9f;  // exp(-20)
        float v[3];
#pragma unroll
        for (int j = 0; j < 3; j++) {
            const float e = s + (float)j;
            const float u = fabsf(x - e);
            float val = 0.0f;
            if (u < 1.5f && e < 63.5f) {
                const float z  = 20.0f * u;
                const float P  = __expf(-z);
                const float S  = 1.0f + P;
                const float qq = fmaf(20.0f, P, 20.0f);  // 20S
                const float Nu = fmaf(z, P, qq);         // 20S + zP
                const float Nl = qq - z;                 // 20S - z
                const float num = P * Nu * Nl;
                const float den = 400.0f * (P + Aexp) * (S * S);
                val = __fdividef(num, den);
            }
            v[j] = val;
        }

        float4 a  = make_float4(0.f, 0.f, 0.f, 0.f);
        float4 bq = make_float4(0.f, 0.f, 0.f, 0.f);
        a.x  = (off0 == 0) ? v[0] : 0.f;
        a.y  = (off0 == 0) ? v[1] : ((off0 == 1) ? v[0] : 0.f);
        a.z  = (off0 == 0) ? v[2] : ((off0 == 1) ? v[1] : ((off0 == 2) ? v[0] : 0.f));
        a.w  = (off0 == 1) ? v[2] : ((off0 == 2) ? v[1] : ((off0 == 3) ? v[0] : 0.f));
        bq.x = (off0 == 2) ? v[2] : ((off0 == 3) ? v[1] : 0.f);
        bq.y = (off0 == 3) ? v[2] : 0.f;

        q[0][tid] = a;
        q[1][tid] = bq;
        c0s[tid]  = c0;
    }
    __syncwarp();   // producer==consumer warp for every SMEM row -> warp fence suffices

    // ---------------- Phase 2: per-warp sequential streaming ----------------
    const int warp = tid >> 5;
    const int lane = tid & 31;
    // warp w owns rows [w*32, w*32+32): 32 rows * 16 chunks = 512 chunks,
    // contiguous 8KB per warp, 16 iterations of 512B stores.
    float4* out4 = reinterpret_cast<float4*>(scores_out)
                 + (size_t)row0 * 16 + warp * 512;
    const int rbase = warp * 32;
#pragma unroll
    for (int i = 0; i < 16; i++) {
        const int g = i * 32 + lane;          // chunk within warp's run
        const int r = rbase + (g >> 4);       // local row
        const int c = g & 15;
        const unsigned d = (unsigned)(c - c0s[r]);
        float4 vst = make_float4(0.f, 0.f, 0.f, 0.f);
        if (d <= 1u)
            vst = q[d][r];
        __stcs(out4 + g, vst);                // evict-first STG.128
    }
}

extern "C" void kernel_launch(void* const* d_in, const int* in_sizes, int n_in,
                              void* d_out, int out_size)
{
    const float* opcode = (const float*)d_in[0];
    float* out = (float*)d_out;
    const int B = in_sizes[0];

    float* idx_out = out + (size_t)B * 64;

    moe_router_kernel<<<B / RPB, NTHREADS>>>(opcode, out, idx_out);
}

// round 16
// speedup vs baseline: 1.0148x; 1.0148x over previous
#include <cuda_runtime.h>
#include <cuda_bf16.h>

// MoERouter — FINAL (best config, 6 samples: 80.29/80.54/80.64/80.83/80.86/80.89us,
// rel_err 6.4e-6). Session: 178.8us (first correct) -> 80.3us, ~86% of HBM spec.
//
// Design rationale (every alternative below was measured and lost):
//  * Math: scores[b][e] = st(d+0.5)*st(0.5-d), d=x-e, SCALE=20. Only experts
//    {m-1, m, m+1} (m = nearest int) exceed ~2.3e-5 -> rest written as exact 0.
//    Closed form with u=|x-e|, z=20u, P=exp(-z), S=1+P, A=exp(-20):
//      score = P*(20S+zP)*(20S-z) / (400*(P+A)*S^2)
//    = 1 EX2 + 1 RCP per nonzero element (fma 8%, alu 19%, issue 26% — idle).
//    argmax = m analytically; exact tie x=k+0.5 -> lower index (jnp.argmax).
//  * Stores: compulsory 553MB write stream binds at ~6.9TB/s (~86% of spec).
//    .cs beats default & .wt (+8.4us); STG.128 beats STG.256 (+7.6us);
//    8KB contiguous warp runs beat 4KB-strided (+8.9us) and 16KB (+3.5us);
//    RPB 256 == 128, 512 regresses (+3.4us); __syncthreads beats __syncwarp
//    (+0.7us: block barrier keeps the 8 store streams phase-aligned).
//
// Phase 1: 1 thread/row computes 3 window values -> two chunk-aligned float4s
//          in SMEM (static placement via selects); idx stored evict-first.
// Phase 2: warp w streams rows [w*32, w*32+32) = contiguous 8KB via STG.128.CS.

#define RPB 256
#define NTHREADS 256

__global__ __launch_bounds__(NTHREADS)
void moe_router_kernel(const float* __restrict__ opcode,
                       float* __restrict__ scores_out,
                       float* __restrict__ idx_out)
{
    __shared__ float4 q[2][RPB];   // q[d][r]: float4 for chunk c0(r)+d
    __shared__ int    c0s[RPB];

    const int tid  = threadIdx.x;
    const int row0 = blockIdx.x * RPB;

    // ---------------- Phase 1: per-row window ----------------
    {
        const int b = row0 + tid;
        const float x = __ldg(opcode + b);

        float m = floorf(x + 0.5f);
        if (m - x == 0.5f) m -= 1.0f;      // exact tie -> lower index
        m = fminf(m, 63.0f);
        __stcs(idx_out + b, m);

        const float s  = fmaxf(m - 1.0f, 0.0f);
        const int   si = (int)s;
        const int   c0 = si >> 2;
        const int   off0 = si & 3;

        const float Aexp = 2.0611536e-9f;  // exp(-20)
        float v[3];
#pragma unroll
        for (int j = 0; j < 3; j++) {
            const float e = s + (float)j;
            const float u = fabsf(x - e);
            float val = 0.0f;
            if (u < 1.5f && e < 63.5f) {
                const float z  = 20.0f * u;
                const float P  = __expf(-z);
                const float S  = 1.0f + P;
                const float qq = fmaf(20.0f, P, 20.0f);  // 20S
                const float Nu = fmaf(z, P, qq);         // 20S + zP
                const float Nl = qq - z;                 // 20S - z
                const float num = P * Nu * Nl;
                const float den = 400.0f * (P + Aexp) * (S * S);
                val = __fdividef(num, den);
            }
            v[j] = val;
        }

        float4 a  = make_float4(0.f, 0.f, 0.f, 0.f);
        float4 bq = make_float4(0.f, 0.f, 0.f, 0.f);
        a.x  = (off0 == 0) ? v[0] : 0.f;
        a.y  = (off0 == 0) ? v[1] : ((off0 == 1) ? v[0] : 0.f);
        a.z  = (off0 == 0) ? v[2] : ((off0 == 1) ? v[1] : ((off0 == 2) ? v[0] : 0.f));
        a.w  = (off0 == 1) ? v[2] : ((off0 == 2) ? v[1] : ((off0 == 3) ? v[0] : 0.f));
        bq.x = (off0 == 2) ? v[2] : ((off0 == 3) ? v[1] : 0.f);
        bq.y = (off0 == 3) ? v[2] : 0.f;

        q[0][tid] = a;
        q[1][tid] = bq;
        c0s[tid]  = c0;
    }
    __syncthreads();

    // ---------------- Phase 2: per-warp sequential streaming ----------------
    const int warp = tid >> 5;
    const int lane = tid & 31;
    // warp w owns rows [w*32, w*32+32): 32 rows * 16 chunks = 512 chunks,
    // contiguous 8KB per warp, 16 iterations of 512B stores.
    float4* out4 = reinterpret_cast<float4*>(scores_out)
                 + (size_t)row0 * 16 + warp * 512;
    const int rbase = warp * 32;
#pragma unroll
    for (int i = 0; i < 16; i++) {
        const int g = i * 32 + lane;          // chunk within warp's run
        const int r = rbase + (g >> 4);       // local row
        const int c = g & 15;
        const unsigned d = (unsigned)(c - c0s[r]);
        float4 vst = make_float4(0.f, 0.f, 0.f, 0.f);
        if (d <= 1u)
            vst = q[d][r];
        __stcs(out4 + g, vst);                // evict-first STG.128
    }
}

extern "C" void kernel_launch(void* const* d_in, const int* in_sizes, int n_in,
                              void* d_out, int out_size)
{
    const float* opcode = (const float*)d_in[0];
    float* out = (float*)d_out;
    const int B = in_sizes[0];

    float* idx_out = out + (size_t)B * 64;

    moe_router_kernel<<<B / RPB, NTHREADS>>>(opcode, out, idx_out);
}